// round 7
// baseline (speedup 1.0000x reference)
#include <cuda_runtime.h>
#include <cuda_bf16.h>
#include <stdint.h>
#include <math.h>

// Shapes (fixed): x [32, 512, 2048] f32, codebook [1024, 512] f32.
#define NB 32
#define CD 512
#define TD 2048
#define KC 1024
#define NT_ROWS (NB * TD)
#define XD_ELEMS ((long long)NB * CD * TD)

#define ROWS_PER_CTA 128
#define N_SCREEN_CTAS (NT_ROWS / ROWS_PER_CTA)   // 512
#define TOPK 8
#define MARGIN 3.5f

// smem layout (bytes), int8 screen
#define A_ST_B 528                 // 512 s8 + 16 pad; 528 % 128 = 16 -> LDSM conflict-free
#define B_ST_B 272                 // 256 s8 + 16 pad
#define SM_AS 0                    // A: 128*528 = 67584
#define SM_BS 67584                // B: 2 x 34816
#define BBUF  34816
#define SM_TV (SM_BS + 2 * BBUF)   // 137216: per-lane top-4 vals 32*256*4 = 32768
#define SM_TI (SM_TV + 32768)      // 169984: per-lane top-4 idx u16 = 16384
#define SM_TOTAL (SM_TI + 16384)   // 186368
// merge scratch (reuses B region): per row 4 wn-lists of 8 -> 128*32*4B = 16KB each
#define SM_MV SM_BS
#define SM_MI (SM_BS + 16384)

// ---- global scratch (no cudaMalloc allowed) ----
__device__ __align__(16) unsigned char g_cb_s8[KC * CD];   // 512 KB quantized codebook
__device__ float g_cscale[KC];        // per-code quant scale (absmax/127)
__device__ float g_half_hat[KC];      // 0.5*||c_hat||^2 of the dequantized code
__device__ float g_half_exact[KC];    // 0.5*||c||^2 fp32 (rescore)
__device__ unsigned int g_xmax_bits;  // absmax of x (float bits, >=0)
__device__ __align__(16) float g_scr_v[NT_ROWS * TOPK];
__device__ __align__(16) int   g_scr_i[NT_ROWS * TOPK];

// ---------------------------------------------------------------------------
__global__ void vq_zero_kernel() { g_xmax_bits = 0u; }

// global absmax of x (order-independent -> deterministic under graph replay)
__global__ void vq_xmax_kernel(const float* __restrict__ x)
{
    const int tid = blockIdx.x * 256 + threadIdx.x;   // 512*256 threads
    float m = 0.0f;
    const float4* xv = reinterpret_cast<const float4*>(x);
#pragma unroll 4
    for (int i = 0; i < 64; ++i) {
        const float4 v = __ldg(xv + (size_t)tid + (size_t)i * 131072);
        m = fmaxf(m, fmaxf(fmaxf(fabsf(v.x), fabsf(v.y)),
                           fmaxf(fabsf(v.z), fabsf(v.w))));
    }
#pragma unroll
    for (int o = 16; o > 0; o >>= 1) m = fmaxf(m, __shfl_xor_sync(~0u, m, o));
    __shared__ float ws[8];
    if ((threadIdx.x & 31) == 0) ws[threadIdx.x >> 5] = m;
    __syncthreads();
    if (threadIdx.x == 0) {
        float bm = ws[0];
#pragma unroll
        for (int j = 1; j < 8; ++j) bm = fmaxf(bm, ws[j]);
        atomicMax(&g_xmax_bits, __float_as_uint(bm));
    }
}

// ===========================================================================
// Codebook prep: per-row absmax scale, s8 quantize, exact + hat half-norms.
// ===========================================================================
__global__ void vq_prep_kernel(const float* __restrict__ cb)
{
    const int k = blockIdx.x;
    const int tid = threadIdx.x;                    // 128 threads x float4
    const float4 v = reinterpret_cast<const float4*>(cb + (size_t)k * CD)[tid];

    float am = fmaxf(fmaxf(fabsf(v.x), fabsf(v.y)), fmaxf(fabsf(v.z), fabsf(v.w)));
    float se = v.x * v.x + v.y * v.y + v.z * v.z + v.w * v.w;
#pragma unroll
    for (int o = 16; o > 0; o >>= 1) {
        am = fmaxf(am, __shfl_xor_sync(~0u, am, o));
        se += __shfl_xor_sync(~0u, se, o);
    }
    __shared__ float wam[4], wse[4];
    __shared__ int   wsq[4];
    if ((tid & 31) == 0) { wam[tid >> 5] = am; wse[tid >> 5] = se; }
    __syncthreads();
    const float absmax = fmaxf(fmaxf(fmaxf(wam[0], wam[1]), fmaxf(wam[2], wam[3])), 1e-20f);
    const float inv = 127.0f / absmax;

    int q0 = max(-127, min(127, __float2int_rn(v.x * inv)));
    int q1 = max(-127, min(127, __float2int_rn(v.y * inv)));
    int q2 = max(-127, min(127, __float2int_rn(v.z * inv)));
    int q3 = max(-127, min(127, __float2int_rn(v.w * inv)));
    uint32_t w = (uint32_t)(q0 & 255) | ((uint32_t)(q1 & 255) << 8) |
                 ((uint32_t)(q2 & 255) << 16) | ((uint32_t)(q3 & 255) << 24);
    reinterpret_cast<uint32_t*>(g_cb_s8)[(size_t)k * (CD / 4) + tid] = w;

    int sq = q0 * q0 + q1 * q1 + q2 * q2 + q3 * q3;
#pragma unroll
    for (int o = 16; o > 0; o >>= 1) sq += __shfl_xor_sync(~0u, sq, o);
    if ((tid & 31) == 0) wsq[tid >> 5] = sq;
    __syncthreads();
    if (tid == 0) {
        const float sc = absmax / 127.0f;
        g_cscale[k]     = sc;
        g_half_exact[k] = 0.5f * (wse[0] + wse[1] + wse[2] + wse[3]);
        g_half_hat[k]   = 0.5f * sc * sc * (float)(wsq[0] + wsq[1] + wsq[2] + wsq[3]);
    }
}

// ---------------------------------------------------------------------------
__device__ __forceinline__ void imma16832(int* d, const uint32_t* a,
                                          const uint32_t* b)
{
    asm volatile(
        "mma.sync.aligned.m16n8k32.row.col.s32.s8.s8.s32 "
        "{%0,%1,%2,%3}, {%4,%5,%6,%7}, {%8,%9}, {%0,%1,%2,%3};"
        : "+r"(d[0]), "+r"(d[1]), "+r"(d[2]), "+r"(d[3])
        : "r"(a[0]), "r"(a[1]), "r"(a[2]), "r"(a[3]), "r"(b[0]), "r"(b[1]));
}
__device__ __forceinline__ void ldsm_x4(uint32_t* r, uint32_t addr)
{
    asm volatile("ldmatrix.sync.aligned.m8n8.x4.shared.b16 {%0,%1,%2,%3}, [%4];"
                 : "=r"(r[0]), "=r"(r[1]), "=r"(r[2]), "=r"(r[3]) : "r"(addr));
}
__device__ __forceinline__ uint32_t smem_u32(const void* p)
{
    uint32_t a;
    asm("{ .reg .u64 t; cvta.to.shared.u64 t, %1; cvt.u32.u64 %0, t; }"
        : "=r"(a) : "l"(p));
    return a;
}

// sorted-desc insert into 4-entry smem list (vals f32 [slot*4+j][256], idx u16)
__device__ __forceinline__ void ins4(float* tvs, unsigned short* tis, int tid,
                                     int slot, float v, int idx)
{
    const int b = (slot << 2) * 256 + tid;
    if (v > tvs[b + 768]) {
        const float v0 = tvs[b], v1 = tvs[b + 256], v2 = tvs[b + 512];
        const unsigned short i0 = tis[b], i1 = tis[b + 256], i2 = tis[b + 512];
        if (v > v2) {
            tvs[b + 768] = v2; tis[b + 768] = i2;
            if (v > v1) {
                tvs[b + 512] = v1; tis[b + 512] = i1;
                if (v > v0) {
                    tvs[b + 256] = v0; tis[b + 256] = i0;
                    tvs[b] = v; tis[b] = (unsigned short)idx;
                } else { tvs[b + 256] = v; tis[b + 256] = (unsigned short)idx; }
            } else { tvs[b + 512] = v; tis[b + 512] = (unsigned short)idx; }
        } else { tvs[b + 768] = v; tis[b + 768] = (unsigned short)idx; }
    }
}

// reg-side sorted-desc insert into 8-entry list (fully unrolled bubble)
__device__ __forceinline__ void rins8(float* v, int* i, float nv, int ni)
{
    if (nv > v[7]) {
        v[7] = nv; i[7] = ni;
#pragma unroll
        for (int p = 7; p > 0; --p) {
            if (v[p] > v[p - 1]) {
                const float tv = v[p - 1]; v[p - 1] = v[p]; v[p] = tv;
                const int   ti = i[p - 1]; i[p - 1] = i[p]; i[p] = ti;
            }
        }
    }
}

// ===========================================================================
// int8 IMMA screen. 512 CTAs x 256 thr (8 warps, 2x4 warp grid; warp tile
// 64 rows x 32 codes, k32 steps). A (128x512 s8) resident; B streamed in
// 256-byte k-chunks, double buffered. Per-lane top-4 -> per-row top-8.
// ===========================================================================
__global__ __launch_bounds__(256, 1) void vq_screen_kernel(const float* __restrict__ x)
{
    extern __shared__ __align__(16) char smem[];
    float*          tvs = reinterpret_cast<float*>(smem + SM_TV);
    unsigned short* tis = reinterpret_cast<unsigned short*>(smem + SM_TI);

    const uint32_t a_base = smem_u32(smem) + SM_AS;
    const uint32_t b_base = smem_u32(smem) + SM_BS;

    const int tid  = threadIdx.x;
    const int lane = tid & 31;
    const int wid  = tid >> 5;
    const int wm   = wid >> 2;          // 0..1  (64 rows each)
    const int wn   = wid & 3;           // 0..3  (32 codes each)
    const int g8   = lane >> 2;         // 0..7
    const int t4   = lane & 3;          // 0..3

    // ldmatrix lane offsets (bytes). A x4: (m0-7,k0-15)(m8-15,k0-15)(m0-7,k16-31)(m8-15,k16-31)
    const uint32_t a_lane_off =
        (uint32_t)(((lane & 7) + ((lane >> 3) & 1) * 8) * A_ST_B + (lane >> 4) * 16);
    // B x4: (n0-7,k0)(n0-7,k16)(n8-15,k0)(n8-15,k16)
    const uint32_t b_lane_off =
        (uint32_t)((lane & 7) * B_ST_B + ((lane >> 3) & 1) * 16 +
                   (lane >> 4) * (8 * B_ST_B));

    const int r0 = blockIdx.x * ROWS_PER_CTA;
    const int n  = r0 >> 11;
    const int t0 = r0 & (TD - 1);

    const float xmax = __uint_as_float(g_xmax_bits);
    const float sx   = xmax * (1.0f / 127.0f);

    // ---- stage A: quantize x[n, :, t0..t0+127] to s8 [row=t][c], padded ----
    {
        const int t   = tid & 127;
        const int cph = tid >> 7;                    // half of c range
        const float* xb = x + (size_t)n * CD * TD + t0 + t;
        const float inv_dx = 127.0f / xmax;
        char* arow = smem + SM_AS + (size_t)t * A_ST_B + cph * 256;
        for (int u = 0; u < 16; ++u) {               // 16B units
            uint32_t w[4];
#pragma unroll
            for (int wi = 0; wi < 4; ++wi) {
                uint32_t acc = 0;
#pragma unroll
                for (int b = 0; b < 4; ++b) {
                    const int c = cph * 256 + u * 16 + wi * 4 + b;
                    const float v = __ldg(xb + (size_t)c * TD);
                    int q = __float2int_rn(v * inv_dx);
                    q = max(-127, min(127, q));
                    acc |= (uint32_t)(q & 255) << (8 * b);
                }
                w[wi] = acc;
            }
            *reinterpret_cast<uint4*>(arow + u * 16) = make_uint4(w[0], w[1], w[2], w[3]);
        }
    }
#pragma unroll
    for (int s = 0; s < 32; ++s) tvs[s * 256 + tid] = -INFINITY;
#pragma unroll
    for (int s = 0; s < 32; ++s) tis[s * 256 + tid] = 0;

    // B staging: chunk = 128 codes x 256 k-bytes = 2048 x 16B units
    uint4 pb[8];
    auto b_fetch = [&](int ntile, int kc) {
#pragma unroll
        for (int i = 0; i < 8; ++i) {
            const int idx = tid + i * 256;
            pb[i] = *reinterpret_cast<const uint4*>(
                g_cb_s8 + (size_t)(ntile * 128 + (idx >> 4)) * CD + kc * 256 +
                (idx & 15) * 16);
        }
    };
    auto b_store = [&](int bb) {
        char* B = smem + SM_BS + bb * BBUF;
#pragma unroll
        for (int i = 0; i < 8; ++i) {
            const int idx = tid + i * 256;
            *reinterpret_cast<uint4*>(B + (size_t)(idx >> 4) * B_ST_B + (idx & 15) * 16) = pb[i];
        }
    };

    b_fetch(0, 0);
    b_store(0);
    __syncthreads();     // A staged + list init + B chunk 0 ready

    int acc[4][4][4];
    // ---- main: 16 global chunks (8 ntiles x 2 k-halves) ----
    for (int gk = 0; gk < 16; ++gk) {
        const int nb = gk >> 1, kb = gk & 1;
        if (kb == 0) {
#pragma unroll
            for (int a = 0; a < 4; ++a)
#pragma unroll
                for (int b = 0; b < 4; ++b)
#pragma unroll
                    for (int c = 0; c < 4; ++c) acc[a][b][c] = 0;
        }
        if (gk < 15) b_fetch((gk + 1) >> 1, (gk + 1) & 1);

        const uint32_t bbuf = b_base + (uint32_t)((gk & 1) * BBUF);
#pragma unroll
        for (int s = 0; s < 8; ++s) {                 // k32 steps in this 256B chunk
            uint32_t bf[2][4];
            ldsm_x4(bf[0], bbuf + (uint32_t)((wn * 32 +  0) * B_ST_B + s * 32) + b_lane_off);
            ldsm_x4(bf[1], bbuf + (uint32_t)((wn * 32 + 16) * B_ST_B + s * 32) + b_lane_off);
#pragma unroll
            for (int mt = 0; mt < 4; ++mt) {
                uint32_t af[4];
                ldsm_x4(af, a_base +
                    (uint32_t)((wm * 64 + mt * 16) * A_ST_B + kb * 256 + s * 32) +
                    a_lane_off);
                imma16832(acc[mt][0], af, &bf[0][0]);
                imma16832(acc[mt][1], af, &bf[0][2]);
                imma16832(acc[mt][2], af, &bf[1][0]);
                imma16832(acc[mt][3], af, &bf[1][2]);
            }
        }

        if (kb == 1) {   // fold this ntile into per-lane top-4 lists
            const int Nb = nb * 128;
#pragma unroll
            for (int nt = 0; nt < 4; ++nt) {
                const int c2 = Nb + wn * 32 + nt * 8 + 2 * t4;
                const float s0 = sx * __ldg(&g_cscale[c2]);
                const float s1 = sx * __ldg(&g_cscale[c2 + 1]);
                const float h0 = __ldg(&g_half_hat[c2]);
                const float h1 = __ldg(&g_half_hat[c2 + 1]);
#pragma unroll
                for (int mt = 0; mt < 4; ++mt) {
                    ins4(tvs, tis, tid, mt * 2,     (float)acc[mt][nt][0] * s0 - h0, c2);
                    ins4(tvs, tis, tid, mt * 2,     (float)acc[mt][nt][1] * s1 - h1, c2 + 1);
                    ins4(tvs, tis, tid, mt * 2 + 1, (float)acc[mt][nt][2] * s0 - h0, c2);
                    ins4(tvs, tis, tid, mt * 2 + 1, (float)acc[mt][nt][3] * s1 - h1, c2 + 1);
                }
            }
        }
        if (gk < 15) b_store((gk + 1) & 1);
        __syncthreads();
    }

    float* mv = reinterpret_cast<float*>(smem + SM_MV);   // [row][wn][8]
    int*   mi = reinterpret_cast<int*>(smem + SM_MI);

    // quad merge (lanes t4=0..3 share rows) -> top-8, one lane writes per slot
#pragma unroll
    for (int slot = 0; slot < 8; ++slot) {
        float v8[8]; int i8[8];
#pragma unroll
        for (int j = 0; j < 4; ++j) {
            v8[j] = tvs[(slot * 4 + j) * 256 + tid];
            i8[j] = (int)tis[(slot * 4 + j) * 256 + tid];
        }
#pragma unroll
        for (int j = 4; j < 8; ++j) { v8[j] = -INFINITY; i8[j] = 0; }
#pragma unroll
        for (int off = 1; off <= 2; off <<= 1) {
            float ov[8]; int oi[8];
#pragma unroll
            for (int j = 0; j < 8; ++j) {
                ov[j] = __shfl_xor_sync(~0u, v8[j], off);
                oi[j] = __shfl_xor_sync(~0u, i8[j], off);
            }
#pragma unroll
            for (int j = 0; j < 8; ++j) rins8(v8, i8, ov[j], oi[j]);
        }
        if (t4 == 0) {
            const int row = wm * 64 + (slot >> 1) * 16 + g8 + (slot & 1) * 8;
            const int e = (row * 4 + wn) * 8;
#pragma unroll
            for (int j = 0; j < 8; ++j) { mv[e + j] = v8[j]; mi[e + j] = i8[j]; }
        }
    }
    __syncthreads();

    if (tid < 128) {    // final per-row merge of the 4 warp_n lists -> top-8
        float v8[8]; int i8[8];
#pragma unroll
        for (int j = 0; j < 8; ++j) { v8[j] = -INFINITY; i8[j] = 0; }
#pragma unroll
        for (int e = 0; e < 32; ++e)
            rins8(v8, i8, mv[tid * 32 + e], mi[tid * 32 + e]);
        const size_t r = (size_t)(r0 + tid);
#pragma unroll
        for (int j = 0; j < 8; j += 4) {
            *reinterpret_cast<float4*>(&g_scr_v[r * TOPK + j]) =
                make_float4(v8[j], v8[j + 1], v8[j + 2], v8[j + 3]);
            *reinterpret_cast<int4*>(&g_scr_i[r * TOPK + j]) =
                make_int4(i8[j], i8[j + 1], i8[j + 2], i8[j + 3]);
        }
    }
}

// ===========================================================================
// Exact fp32 rescore of top-8 candidates within margin, then gather-write.
// ===========================================================================
__global__ __launch_bounds__(128) void vq_rescore_gather_kernel(
    const float* __restrict__ x, const float* __restrict__ cb,
    float* __restrict__ out, long long out_size)
{
    const int r = blockIdx.x * 128 + threadIdx.x;
    const int n = r >> 11;
    const int t = r & (TD - 1);

    float cv[TOPK]; int ci[TOPK];
#pragma unroll
    for (int j = 0; j < TOPK; j += 4) {
        const float4 sv = *reinterpret_cast<const float4*>(&g_scr_v[(size_t)r * TOPK + j]);
        const int4   si = *reinterpret_cast<const int4*>(&g_scr_i[(size_t)r * TOPK + j]);
        cv[j] = sv.x; cv[j + 1] = sv.y; cv[j + 2] = sv.z; cv[j + 3] = sv.w;
        ci[j] = si.x; ci[j + 1] = si.y; ci[j + 2] = si.z; ci[j + 3] = si.w;
    }
    const float thr = cv[0] - MARGIN;

    const float* xp = x + (size_t)n * CD * TD + t;

    float best;
    {
        const float* c0 = cb + (size_t)ci[0] * CD;
        float a = 0.0f;
#pragma unroll 8
        for (int c = 0; c < CD; ++c)
            a = fmaf(__ldg(xp + (size_t)c * TD), __ldg(c0 + c), a);
        best = a - __ldg(&g_half_exact[ci[0]]);
    }
    int bidx = ci[0];

#pragma unroll
    for (int m = 1; m < TOPK; ++m) {
        if (cv[m] >= thr) {            // rare: expected ~0.1 extra rescores/row
            const float* cm = cb + (size_t)ci[m] * CD;
            float a = 0.0f;
#pragma unroll 8
            for (int c = 0; c < CD; ++c)
                a = fmaf(__ldg(xp + (size_t)c * TD), __ldg(cm + c), a);
            const float s = a - __ldg(&g_half_exact[ci[m]]);
            if (s > best || (s == best && ci[m] < bidx)) { best = s; bidx = ci[m]; }
        }
    }

    const float4* crow = reinterpret_cast<const float4*>(cb + (size_t)bidx * CD);
    float* ob = out + (size_t)n * CD * TD + t;
#pragma unroll 4
    for (int c4 = 0; c4 < CD / 4; ++c4) {
        const float4 w = __ldg(crow + c4);
        ob[(size_t)(c4 * 4 + 0) * TD] = w.x;
        ob[(size_t)(c4 * 4 + 1) * TD] = w.y;
        ob[(size_t)(c4 * 4 + 2) * TD] = w.z;
        ob[(size_t)(c4 * 4 + 3) * TD] = w.w;
    }
    if (r == 0) {
        for (long long e = XD_ELEMS; e < out_size; ++e) out[e] = 0.0f;
    }
}

// ===========================================================================
extern "C" void kernel_launch(void* const* d_in, const int* in_sizes, int n_in,
                              void* d_out, int out_size)
{
    const float* x  = (const float*)d_in[0];
    const float* cb = (const float*)d_in[1];
    if (n_in >= 2 && in_sizes[0] < in_sizes[1]) {
        const float* tmp = x; x = cb; cb = tmp;
    }
    float* out = (float*)d_out;

    cudaFuncSetAttribute(vq_screen_kernel,
                         cudaFuncAttributeMaxDynamicSharedMemorySize, SM_TOTAL);

    vq_zero_kernel<<<1, 1>>>();
    vq_xmax_kernel<<<512, 256>>>(x);
    vq_prep_kernel<<<KC, 128>>>(cb);
    vq_screen_kernel<<<N_SCREEN_CTAS, 256, SM_TOTAL>>>(x);
    vq_rescore_gather_kernel<<<NT_ROWS / 128, 128>>>(x, cb, out, (long long)out_size);
}

// round 9
// speedup vs baseline: 1.9266x; 1.9266x over previous
#include <cuda_runtime.h>
#include <stdint.h>
#include <math.h>

// Shapes (fixed): x [32, 512, 2048] f32, codebook [1024, 512] f32.
#define NB 32
#define CD 512
#define TD 2048
#define KC 1024
#define NT_ROWS (NB * TD)
#define XD_ELEMS ((long long)NB * CD * TD)

#define ROWS_PER_CTA 64
#define N_CTAS (NT_ROWS / ROWS_PER_CTA)    // 1024
#define TOPK 8
#define MARGIN 3.5f

// smem layout (bytes)
#define A_ST_B 528                  // 512 s8 + 16 pad (528%128=16 -> LDSM conflict-free)
#define B_ST_B 144                  // 128 s8 + 16 pad
#define SM_AS 0                     // A: 64*528 = 33792
#define SM_BS 33792                 // B: 2 x 18432
#define BBUF  18432
#define SM_TV (SM_BS + 2 * BBUF)    // 70656: per-lane top-4 vals, 4 slots: 16*256*4 = 16384
#define SM_TI (SM_TV + 16384)       // 87040: idx u16: 16*256*2 = 8192
#define SM_RED (SM_TI + 8192)       // 95232: absmax reduce (8 floats) + pad
#define SM_TOTAL (SM_RED + 256)     // 95488  -> 2 CTAs/SM
// reuse regions after their last use:
#define SM_MV SM_BS                 // merge: 64*4*8*4 = 8192
#define SM_MI (SM_BS + 8192)        // 8192
#define SM_FV SM_TV                 // final per-row top8 vals: 64*8*4 = 2048
#define SM_FI (SM_TV + 2048)        // 2048
#define SM_BIX (SM_TV + 4096)       // winning idx per row: 64*4

// ---- global scratch (no cudaMalloc allowed) ----
__device__ __align__(16) unsigned char g_cb_s8[KC * CD];   // 512 KB quantized codebook
__device__ float g_cscale[KC];        // per-code quant scale (absmax/127)
__device__ float g_half_hat[KC];      // 0.5*||c_hat||^2 (dequantized-code norm)
__device__ float g_half_exact[KC];    // 0.5*||c||^2 fp32 (rescore)

// ===========================================================================
// Codebook prep: per-row absmax scale, s8 quantize, exact + hat half-norms.
// ===========================================================================
__global__ void vq_prep_kernel(const float* __restrict__ cb)
{
    const int k = blockIdx.x;
    const int tid = threadIdx.x;                    // 128 threads x float4
    const float4 v = reinterpret_cast<const float4*>(cb + (size_t)k * CD)[tid];

    float am = fmaxf(fmaxf(fabsf(v.x), fabsf(v.y)), fmaxf(fabsf(v.z), fabsf(v.w)));
    float se = v.x * v.x + v.y * v.y + v.z * v.z + v.w * v.w;
#pragma unroll
    for (int o = 16; o > 0; o >>= 1) {
        am = fmaxf(am, __shfl_xor_sync(~0u, am, o));
        se += __shfl_xor_sync(~0u, se, o);
    }
    __shared__ float wam[4], wse[4];
    __shared__ int   wsq[4];
    if ((tid & 31) == 0) { wam[tid >> 5] = am; wse[tid >> 5] = se; }
    __syncthreads();
    const float absmax = fmaxf(fmaxf(fmaxf(wam[0], wam[1]), fmaxf(wam[2], wam[3])), 1e-20f);
    const float inv = 127.0f / absmax;

    int q0 = max(-127, min(127, __float2int_rn(v.x * inv)));
    int q1 = max(-127, min(127, __float2int_rn(v.y * inv)));
    int q2 = max(-127, min(127, __float2int_rn(v.z * inv)));
    int q3 = max(-127, min(127, __float2int_rn(v.w * inv)));
    uint32_t w = (uint32_t)(q0 & 255) | ((uint32_t)(q1 & 255) << 8) |
                 ((uint32_t)(q2 & 255) << 16) | ((uint32_t)(q3 & 255) << 24);
    reinterpret_cast<uint32_t*>(g_cb_s8)[(size_t)k * (CD / 4) + tid] = w;

    int sq = q0 * q0 + q1 * q1 + q2 * q2 + q3 * q3;
#pragma unroll
    for (int o = 16; o > 0; o >>= 1) sq += __shfl_xor_sync(~0u, sq, o);
    if ((tid & 31) == 0) wsq[tid >> 5] = sq;
    __syncthreads();
    if (tid == 0) {
        const float sc = absmax / 127.0f;
        g_cscale[k]     = sc;
        g_half_exact[k] = 0.5f * (wse[0] + wse[1] + wse[2] + wse[3]);
        g_half_hat[k]   = 0.5f * sc * sc * (float)(wsq[0] + wsq[1] + wsq[2] + wsq[3]);
    }
}

// ---------------------------------------------------------------------------
__device__ __forceinline__ void imma16832(int* d, const uint32_t* a,
                                          const uint32_t* b)
{
    asm volatile(
        "mma.sync.aligned.m16n8k32.row.col.s32.s8.s8.s32 "
        "{%0,%1,%2,%3}, {%4,%5,%6,%7}, {%8,%9}, {%0,%1,%2,%3};"
        : "+r"(d[0]), "+r"(d[1]), "+r"(d[2]), "+r"(d[3])
        : "r"(a[0]), "r"(a[1]), "r"(a[2]), "r"(a[3]), "r"(b[0]), "r"(b[1]));
}
__device__ __forceinline__ void ldsm_x4(uint32_t* r, uint32_t addr)
{
    asm volatile("ldmatrix.sync.aligned.m8n8.x4.shared.b16 {%0,%1,%2,%3}, [%4];"
                 : "=r"(r[0]), "=r"(r[1]), "=r"(r[2]), "=r"(r[3]) : "r"(addr));
}
__device__ __forceinline__ uint32_t smem_u32(const void* p)
{
    uint32_t a;
    asm("{ .reg .u64 t; cvta.to.shared.u64 t, %1; cvt.u32.u64 %0, t; }"
        : "=r"(a) : "l"(p));
    return a;
}

// sorted-desc insert into 4-entry smem list (vals f32 [slot*4+j][256], idx u16)
__device__ __forceinline__ void ins4(float* tvs, unsigned short* tis, int tid,
                                     int slot, float v, int idx)
{
    const int b = (slot << 2) * 256 + tid;
    if (v > tvs[b + 768]) {
        const float v0 = tvs[b], v1 = tvs[b + 256], v2 = tvs[b + 512];
        const unsigned short i0 = tis[b], i1 = tis[b + 256], i2 = tis[b + 512];
        if (v > v2) {
            tvs[b + 768] = v2; tis[b + 768] = i2;
            if (v > v1) {
                tvs[b + 512] = v1; tis[b + 512] = i1;
                if (v > v0) {
                    tvs[b + 256] = v0; tis[b + 256] = i0;
                    tvs[b] = v; tis[b] = (unsigned short)idx;
                } else { tvs[b + 256] = v; tis[b + 256] = (unsigned short)idx; }
            } else { tvs[b + 512] = v; tis[b + 512] = (unsigned short)idx; }
        } else { tvs[b + 768] = v; tis[b + 768] = (unsigned short)idx; }
    }
}
// reg-side sorted-desc insert into 8-entry list
__device__ __forceinline__ void rins8(float* v, int* i, float nv, int ni)
{
    if (nv > v[7]) {
        v[7] = nv; i[7] = ni;
#pragma unroll
        for (int p = 7; p > 0; --p) {
            if (v[p] > v[p - 1]) {
                const float tv = v[p - 1]; v[p - 1] = v[p]; v[p] = tv;
                const int   ti = i[p - 1]; i[p - 1] = i[p]; i[p] = ti;
            }
        }
    }
}

// ===========================================================================
// Fused: per-CTA x-scale -> s8 quantize -> IMMA screen -> top-8 -> exact
// fp32 rescore (quad-convergent shuffles!) -> gather-write.
// 1024 CTAs x 256 thr; 2 CTAs/SM. Warp grid 2(wm) x 4(wn), tile 32x32.
// ===========================================================================
__global__ __launch_bounds__(256, 2) void vq_fused_kernel(
    const float* __restrict__ x, const float* __restrict__ cb,
    float* __restrict__ out, long long out_size)
{
    extern __shared__ __align__(16) char smem[];
    float*          tvs = reinterpret_cast<float*>(smem + SM_TV);
    unsigned short* tis = reinterpret_cast<unsigned short*>(smem + SM_TI);
    float*          red = reinterpret_cast<float*>(smem + SM_RED);

    const uint32_t a_base = smem_u32(smem) + SM_AS;
    const uint32_t b_base = smem_u32(smem) + SM_BS;

    const int tid  = threadIdx.x;
    const int lane = tid & 31;
    const int wid  = tid >> 5;
    const int wm   = wid >> 2;          // 0..1 (32 rows each)
    const int wn   = wid & 3;           // 0..3 (32 codes each)
    const int g8   = lane >> 2;         // 0..7
    const int t4   = lane & 3;          // 0..3

    // ldmatrix lane byte offsets
    const uint32_t a_lane_off =
        (uint32_t)(((lane & 7) + ((lane >> 3) & 1) * 8) * A_ST_B + (lane >> 4) * 16);
    const uint32_t b_lane_off =
        (uint32_t)((lane & 7) * B_ST_B + ((lane >> 3) & 1) * 16 +
                   (lane >> 4) * (8 * B_ST_B));

    const int r0 = blockIdx.x * ROWS_PER_CTA;
    const int n  = r0 >> 11;
    const int t0 = r0 & (TD - 1);

    const int trow = tid & 63;          // staging/gather row within slice
    const int cg   = tid >> 6;          // 0..3: 128-channel group
    const float* xrow = x + (size_t)n * CD * TD + t0 + trow;

    // ---- phase 1: per-CTA absmax over the 64x512 slice ----
    float am = 0.0f;
#pragma unroll 8
    for (int i = 0; i < 128; ++i)
        am = fmaxf(am, fabsf(__ldg(xrow + (size_t)(cg * 128 + i) * TD)));
#pragma unroll
    for (int o = 16; o > 0; o >>= 1) am = fmaxf(am, __shfl_xor_sync(~0u, am, o));
    if (lane == 0) red[wid] = am;
    __syncthreads();
    float absmax = red[0];
#pragma unroll
    for (int j = 1; j < 8; ++j) absmax = fmaxf(absmax, red[j]);
    absmax = fmaxf(absmax, 1e-20f);
    const float sx = absmax * (1.0f / 127.0f);
    const float inv_dx = 127.0f / absmax;

    // ---- phase 2: quantize slice to s8 smem A [row][c] (L2-hot re-read) ----
    {
        char* arow = smem + SM_AS + (size_t)trow * A_ST_B + cg * 128;
#pragma unroll 4
        for (int u = 0; u < 32; ++u) {
            uint32_t acc = 0;
#pragma unroll
            for (int b = 0; b < 4; ++b) {
                const float v = __ldg(xrow + (size_t)(cg * 128 + u * 4 + b) * TD);
                int q = __float2int_rn(v * inv_dx);
                q = max(-127, min(127, q));
                acc |= (uint32_t)(q & 255) << (8 * b);
            }
            *reinterpret_cast<uint32_t*>(arow + u * 4) = acc;
        }
    }
#pragma unroll
    for (int s = 0; s < 16; ++s) tvs[s * 256 + tid] = -INFINITY;
#pragma unroll
    for (int s = 0; s < 16; ++s) tis[s * 256 + tid] = 0;

    // B staging: chunk = 128 codes x 128 k-bytes = 1024 x 16B; 4/thread
    uint4 pb[4];
    auto b_fetch = [&](int ntile, int kb) {
#pragma unroll
        for (int i = 0; i < 4; ++i) {
            const int idx = tid + i * 256;
            pb[i] = *reinterpret_cast<const uint4*>(
                g_cb_s8 + (size_t)(ntile * 128 + (idx >> 3)) * CD + kb * 128 +
                (idx & 7) * 16);
        }
    };
    auto b_store = [&](int bb) {
        char* B = smem + SM_BS + bb * BBUF;
#pragma unroll
        for (int i = 0; i < 4; ++i) {
            const int idx = tid + i * 256;
            *reinterpret_cast<uint4*>(B + (size_t)(idx >> 3) * B_ST_B + (idx & 7) * 16) = pb[i];
        }
    };

    b_fetch(0, 0);
    b_store(0);
    __syncthreads();     // A staged + lists init + B chunk 0 ready

    int acc[2][4][4];
    // ---- main: 32 chunks (8 ntiles x 4 k-quarters) ----
    for (int gk = 0; gk < 32; ++gk) {
        const int kb = gk & 3;
        if (kb == 0) {
#pragma unroll
            for (int a = 0; a < 2; ++a)
#pragma unroll
                for (int b = 0; b < 4; ++b)
#pragma unroll
                    for (int c = 0; c < 4; ++c) acc[a][b][c] = 0;
        }
        if (gk < 31) b_fetch((gk + 1) >> 2, (gk + 1) & 3);

        const uint32_t bbuf = b_base + (uint32_t)((gk & 1) * BBUF);
#pragma unroll
        for (int s = 0; s < 4; ++s) {                 // k32 steps in 128B chunk
            uint32_t bf[2][4];
            ldsm_x4(bf[0], bbuf + (uint32_t)((wn * 32 +  0) * B_ST_B + s * 32) + b_lane_off);
            ldsm_x4(bf[1], bbuf + (uint32_t)((wn * 32 + 16) * B_ST_B + s * 32) + b_lane_off);
#pragma unroll
            for (int mt = 0; mt < 2; ++mt) {
                uint32_t af[4];
                ldsm_x4(af, a_base +
                    (uint32_t)((wm * 32 + mt * 16) * A_ST_B + kb * 128 + s * 32) +
                    a_lane_off);
                imma16832(acc[mt][0], af, &bf[0][0]);
                imma16832(acc[mt][1], af, &bf[0][2]);
                imma16832(acc[mt][2], af, &bf[1][0]);
                imma16832(acc[mt][3], af, &bf[1][2]);
            }
        }

        if (kb == 3) {   // fold finished ntile into per-lane top-4 lists
            const int Nb = (gk >> 2) * 128;
#pragma unroll
            for (int nt = 0; nt < 4; ++nt) {
                const int c2 = Nb + wn * 32 + nt * 8 + 2 * t4;
                const float s0 = sx * __ldg(&g_cscale[c2]);
                const float s1 = sx * __ldg(&g_cscale[c2 + 1]);
                const float h0 = __ldg(&g_half_hat[c2]);
                const float h1 = __ldg(&g_half_hat[c2 + 1]);
#pragma unroll
                for (int mt = 0; mt < 2; ++mt) {
                    ins4(tvs, tis, tid, mt * 2,     (float)acc[mt][nt][0] * s0 - h0, c2);
                    ins4(tvs, tis, tid, mt * 2,     (float)acc[mt][nt][1] * s1 - h1, c2 + 1);
                    ins4(tvs, tis, tid, mt * 2 + 1, (float)acc[mt][nt][2] * s0 - h0, c2);
                    ins4(tvs, tis, tid, mt * 2 + 1, (float)acc[mt][nt][3] * s1 - h1, c2 + 1);
                }
            }
        }
        if (gk < 31) b_store((gk + 1) & 1);
        __syncthreads();
    }

    float* mv = reinterpret_cast<float*>(smem + SM_MV);   // [row][wn][8]
    int*   mi = reinterpret_cast<int*>(smem + SM_MI);

    // quad merge (lanes t4=0..3 share rows) -> top-8, one lane writes per slot
#pragma unroll
    for (int slot = 0; slot < 4; ++slot) {
        float v8[8]; int i8[8];
#pragma unroll
        for (int j = 0; j < 4; ++j) {
            v8[j] = tvs[(slot * 4 + j) * 256 + tid];
            i8[j] = (int)tis[(slot * 4 + j) * 256 + tid];
        }
#pragma unroll
        for (int j = 4; j < 8; ++j) { v8[j] = -INFINITY; i8[j] = 0; }
#pragma unroll
        for (int off = 1; off <= 2; off <<= 1) {
            float ov[8]; int oi[8];
#pragma unroll
            for (int j = 0; j < 8; ++j) {
                ov[j] = __shfl_xor_sync(~0u, v8[j], off);
                oi[j] = __shfl_xor_sync(~0u, i8[j], off);
            }
#pragma unroll
            for (int j = 0; j < 8; ++j) rins8(v8, i8, ov[j], oi[j]);
        }
        if (t4 == 0) {
            const int row = wm * 32 + (slot >> 1) * 16 + g8 + (slot & 1) * 8;
            const int e = (row * 4 + wn) * 8;
#pragma unroll
            for (int j = 0; j < 8; ++j) { mv[e + j] = v8[j]; mi[e + j] = i8[j]; }
        }
    }
    __syncthreads();

    float* fv  = reinterpret_cast<float*>(smem + SM_FV);   // [row][8]
    int*   fi  = reinterpret_cast<int*>(smem + SM_FI);
    int*   bix = reinterpret_cast<int*>(smem + SM_BIX);

    if (tid < 64) {      // final per-row merge of the 4 wn-lists -> top-8
        float v8[8]; int i8[8];
#pragma unroll
        for (int j = 0; j < 8; ++j) { v8[j] = -INFINITY; i8[j] = 0; }
#pragma unroll
        for (int e = 0; e < 32; ++e)
            rins8(v8, i8, mv[tid * 32 + e], mi[tid * 32 + e]);
#pragma unroll
        for (int j = 0; j < 8; ++j) { fv[tid * 8 + j] = v8[j]; fi[tid * 8 + j] = i8[j]; }
    }
    __syncthreads();

    // ---- exact fp32 rescore: QUAD = 4 ADJACENT LANES of one warp per row.
    // row = wid*8 + (lane>>2), qcg = lane&3 (128 channels each).
    // The candidate gate (svm >= thr) is row-uniform -> quad-convergent, so
    // quad-masked shuffles are safe (this was the R8 deadlock).
    {
        const int rrow = wid * 8 + (lane >> 2);   // 8 warps x 8 rows = 64
        const int qcg  = lane & 3;
        const unsigned qmask = 0xFu << (lane & ~3);
        const float* xr = x + (size_t)n * CD * TD + t0 + rrow;

        const float thr = fv[rrow * 8] - MARGIN;
        float best = -INFINITY;
        int   bidx = fi[rrow * 8];
#pragma unroll
        for (int m = 0; m < TOPK; ++m) {
            const float svm = fv[rrow * 8 + m];
            if (m == 0 || svm >= thr) {           // uniform within the quad
                const int k = fi[rrow * 8 + m];
                const float* cr = cb + (size_t)k * CD + qcg * 128;
                float a = 0.0f;
#pragma unroll 8
                for (int i = 0; i < 128; ++i)
                    a = fmaf(__ldg(xr + (size_t)(qcg * 128 + i) * TD), __ldg(cr + i), a);
                a += __shfl_xor_sync(qmask, a, 1);
                a += __shfl_xor_sync(qmask, a, 2);
                const float s = a - __ldg(&g_half_exact[k]);
                if (s > best || (s == best && k < bidx)) { best = s; bidx = k; }
            }
        }
        if (qcg == 0) bix[rrow] = bidx;
    }
    __syncthreads();

    // ---- gather-write: thread (cg, trow); stores coalesced over t ----
    {
        const int bidx = bix[trow];
        const float4* cr4 = reinterpret_cast<const float4*>(cb + (size_t)bidx * CD + cg * 128);
        float* ob = out + (size_t)n * CD * TD + t0 + trow;
#pragma unroll 4
        for (int i = 0; i < 32; ++i) {
            const float4 w = __ldg(cr4 + i);
            const int c = cg * 128 + i * 4;
            ob[(size_t)(c + 0) * TD] = w.x;
            ob[(size_t)(c + 1) * TD] = w.y;
            ob[(size_t)(c + 2) * TD] = w.z;
            ob[(size_t)(c + 3) * TD] = w.w;
        }
    }
    if (blockIdx.x == 0 && tid == 0) {   // scalar tail (commit_loss, perplexity)
        for (long long e = XD_ELEMS; e < out_size; ++e) out[e] = 0.0f;
    }
}

// ===========================================================================
extern "C" void kernel_launch(void* const* d_in, const int* in_sizes, int n_in,
                              void* d_out, int out_size)
{
    const float* x  = (const float*)d_in[0];
    const float* cb = (const float*)d_in[1];
    if (n_in >= 2 && in_sizes[0] < in_sizes[1]) {
        const float* tmp = x; x = cb; cb = tmp;
    }
    float* out = (float*)d_out;

    cudaFuncSetAttribute(vq_fused_kernel,
                         cudaFuncAttributeMaxDynamicSharedMemorySize, SM_TOTAL);

    vq_prep_kernel<<<KC, 128>>>(cb);
    vq_fused_kernel<<<N_CTAS, 256, SM_TOTAL>>>(x, cb, out, (long long)out_size);
}

// round 10
// speedup vs baseline: 2.0168x; 1.0468x over previous
#include <cuda_runtime.h>
#include <stdint.h>
#include <math.h>

// Shapes (fixed): x [32, 512, 2048] f32, codebook [1024, 512] f32.
#define NB 32
#define CD 512
#define TD 2048
#define KC 1024
#define NT_ROWS (NB * TD)
#define XD_ELEMS ((long long)NB * CD * TD)

#define ROWS_PER_CTA 64
#define N_CTAS (NT_ROWS / ROWS_PER_CTA)    // 1024
#define TOPK 8
#define MARGIN 3.5f

// smem layout (bytes) — budgeted for 3 CTAs/SM (<= 76800 B with 1KB reserve)
#define A_ST_B 528                  // 512 s8 + 16 pad (528%128=16 -> LDSM conflict-free)
#define B_ST_B 144                  // 128 s8 + 16 pad
#define SM_AS 0                     // A: 64*528 = 33792
#define SM_BS 33792                 // B: ONE 18432-byte buffer (reg-prefetch pipeline)
#define BBUF  18432
#define SM_TV (SM_BS + BBUF)        // 52224: per-lane top-4 vals, 4 slots: 16*256*4 = 16384
#define SM_TI (SM_TV + 16384)       // 68608: idx u16: 16*256*2 = 8192
#define SM_TOTAL (SM_TI + 8192)     // 76800 exactly
// aliased regions (non-overlapping lifetimes):
#define SM_RED SM_TV                // absmax reduce (8 floats), dead before tvs init
#define SM_MV SM_BS                 // merge: 64*4*8*4 = 8192   (B dead after main loop)
#define SM_MI (SM_BS + 8192)        // 8192
#define SM_FV SM_TV                 // final per-row top8 vals: 64*8*4 = 2048
#define SM_FI (SM_TV + 2048)        // 2048
#define SM_BIX (SM_TV + 4096)       // winning idx per row: 64*4

// ---- global scratch (no cudaMalloc allowed) ----
__device__ __align__(16) unsigned char g_cb_s8[KC * CD];   // 512 KB quantized codebook
__device__ float g_cscale[KC];        // per-code quant scale (absmax/127)
__device__ float g_half_hat[KC];      // 0.5*||c_hat||^2 (dequantized-code norm)
__device__ float g_half_exact[KC];    // 0.5*||c||^2 fp32 (rescore)

// ===========================================================================
// Codebook prep: per-row absmax scale, s8 quantize, exact + hat half-norms.
// ===========================================================================
__global__ void vq_prep_kernel(const float* __restrict__ cb)
{
    const int k = blockIdx.x;
    const int tid = threadIdx.x;                    // 128 threads x float4
    const float4 v = reinterpret_cast<const float4*>(cb + (size_t)k * CD)[tid];

    float am = fmaxf(fmaxf(fabsf(v.x), fabsf(v.y)), fmaxf(fabsf(v.z), fabsf(v.w)));
    float se = v.x * v.x + v.y * v.y + v.z * v.z + v.w * v.w;
#pragma unroll
    for (int o = 16; o > 0; o >>= 1) {
        am = fmaxf(am, __shfl_xor_sync(~0u, am, o));
        se += __shfl_xor_sync(~0u, se, o);
    }
    __shared__ float wam[4], wse[4];
    __shared__ int   wsq[4];
    if ((tid & 31) == 0) { wam[tid >> 5] = am; wse[tid >> 5] = se; }
    __syncthreads();
    const float absmax = fmaxf(fmaxf(fmaxf(wam[0], wam[1]), fmaxf(wam[2], wam[3])), 1e-20f);
    const float inv = 127.0f / absmax;

    int q0 = max(-127, min(127, __float2int_rn(v.x * inv)));
    int q1 = max(-127, min(127, __float2int_rn(v.y * inv)));
    int q2 = max(-127, min(127, __float2int_rn(v.z * inv)));
    int q3 = max(-127, min(127, __float2int_rn(v.w * inv)));
    uint32_t w = (uint32_t)(q0 & 255) | ((uint32_t)(q1 & 255) << 8) |
                 ((uint32_t)(q2 & 255) << 16) | ((uint32_t)(q3 & 255) << 24);
    reinterpret_cast<uint32_t*>(g_cb_s8)[(size_t)k * (CD / 4) + tid] = w;

    int sq = q0 * q0 + q1 * q1 + q2 * q2 + q3 * q3;
#pragma unroll
    for (int o = 16; o > 0; o >>= 1) sq += __shfl_xor_sync(~0u, sq, o);
    if ((tid & 31) == 0) wsq[tid >> 5] = sq;
    __syncthreads();
    if (tid == 0) {
        const float sc = absmax / 127.0f;
        g_cscale[k]     = sc;
        g_half_exact[k] = 0.5f * (wse[0] + wse[1] + wse[2] + wse[3]);
        g_half_hat[k]   = 0.5f * sc * sc * (float)(wsq[0] + wsq[1] + wsq[2] + wsq[3]);
    }
}

// ---------------------------------------------------------------------------
__device__ __forceinline__ void imma16832(int* d, const uint32_t* a,
                                          const uint32_t* b)
{
    asm volatile(
        "mma.sync.aligned.m16n8k32.row.col.s32.s8.s8.s32 "
        "{%0,%1,%2,%3}, {%4,%5,%6,%7}, {%8,%9}, {%0,%1,%2,%3};"
        : "+r"(d[0]), "+r"(d[1]), "+r"(d[2]), "+r"(d[3])
        : "r"(a[0]), "r"(a[1]), "r"(a[2]), "r"(a[3]), "r"(b[0]), "r"(b[1]));
}
__device__ __forceinline__ void ldsm_x4(uint32_t* r, uint32_t addr)
{
    asm volatile("ldmatrix.sync.aligned.m8n8.x4.shared.b16 {%0,%1,%2,%3}, [%4];"
                 : "=r"(r[0]), "=r"(r[1]), "=r"(r[2]), "=r"(r[3]) : "r"(addr));
}
__device__ __forceinline__ uint32_t smem_u32(const void* p)
{
    uint32_t a;
    asm("{ .reg .u64 t; cvta.to.shared.u64 t, %1; cvt.u32.u64 %0, t; }"
        : "=r"(a) : "l"(p));
    return a;
}

// sorted-desc insert into 4-entry smem list (vals f32 [slot*4+j][256], idx u16)
__device__ __forceinline__ void ins4(float* tvs, unsigned short* tis, int tid,
                                     int slot, float v, int idx)
{
    const int b = (slot << 2) * 256 + tid;
    if (v > tvs[b + 768]) {
        const float v0 = tvs[b], v1 = tvs[b + 256], v2 = tvs[b + 512];
        const unsigned short i0 = tis[b], i1 = tis[b + 256], i2 = tis[b + 512];
        if (v > v2) {
            tvs[b + 768] = v2; tis[b + 768] = i2;
            if (v > v1) {
                tvs[b + 512] = v1; tis[b + 512] = i1;
                if (v > v0) {
                    tvs[b + 256] = v0; tis[b + 256] = i0;
                    tvs[b] = v; tis[b] = (unsigned short)idx;
                } else { tvs[b + 256] = v; tis[b + 256] = (unsigned short)idx; }
            } else { tvs[b + 512] = v; tis[b + 512] = (unsigned short)idx; }
        } else { tvs[b + 768] = v; tis[b + 768] = (unsigned short)idx; }
    }
}
// reg-side sorted-desc insert into 8-entry list
__device__ __forceinline__ void rins8(float* v, int* i, float nv, int ni)
{
    if (nv > v[7]) {
        v[7] = nv; i[7] = ni;
#pragma unroll
        for (int p = 7; p > 0; --p) {
            if (v[p] > v[p - 1]) {
                const float tv = v[p - 1]; v[p - 1] = v[p]; v[p] = tv;
                const int   ti = i[p - 1]; i[p - 1] = i[p]; i[p] = ti;
            }
        }
    }
}

// ===========================================================================
// Fused: per-CTA x-scale -> s8 quantize -> IMMA screen -> top-8 -> exact
// fp32 rescore (quad-convergent) -> gather-write.
// 1024 CTAs x 256 thr; 3 CTAs/SM (24 warps). Warp grid 2(wm) x 4(wn), 32x32.
// Single B buffer + register prefetch: fetch(next) | compute(cur) | sync |
// store(next) | sync.
// ===========================================================================
__global__ __launch_bounds__(256, 3) void vq_fused_kernel(
    const float* __restrict__ x, const float* __restrict__ cb,
    float* __restrict__ out, long long out_size)
{
    extern __shared__ __align__(16) char smem[];
    float*          tvs = reinterpret_cast<float*>(smem + SM_TV);
    unsigned short* tis = reinterpret_cast<unsigned short*>(smem + SM_TI);
    float*          red = reinterpret_cast<float*>(smem + SM_RED);

    const uint32_t a_base = smem_u32(smem) + SM_AS;
    const uint32_t b_base = smem_u32(smem) + SM_BS;

    const int tid  = threadIdx.x;
    const int lane = tid & 31;
    const int wid  = tid >> 5;
    const int wm   = wid >> 2;          // 0..1 (32 rows each)
    const int wn   = wid & 3;           // 0..3 (32 codes each)
    const int g8   = lane >> 2;         // 0..7
    const int t4   = lane & 3;          // 0..3

    // ldmatrix lane byte offsets
    const uint32_t a_lane_off =
        (uint32_t)(((lane & 7) + ((lane >> 3) & 1) * 8) * A_ST_B + (lane >> 4) * 16);
    const uint32_t b_lane_off =
        (uint32_t)((lane & 7) * B_ST_B + ((lane >> 3) & 1) * 16 +
                   (lane >> 4) * (8 * B_ST_B));

    const int r0 = blockIdx.x * ROWS_PER_CTA;
    const int n  = r0 >> 11;
    const int t0 = r0 & (TD - 1);

    const int trow = tid & 63;          // staging/gather row within slice
    const int cg   = tid >> 6;          // 0..3: 128-channel group
    const float* xrow = x + (size_t)n * CD * TD + t0 + trow;

    // ---- phase 1: per-CTA absmax over the 64x512 slice ----
    float am = 0.0f;
#pragma unroll 8
    for (int i = 0; i < 128; ++i)
        am = fmaxf(am, fabsf(__ldg(xrow + (size_t)(cg * 128 + i) * TD)));
#pragma unroll
    for (int o = 16; o > 0; o >>= 1) am = fmaxf(am, __shfl_xor_sync(~0u, am, o));
    if (lane == 0) red[wid] = am;
    __syncthreads();
    float absmax = red[0];
#pragma unroll
    for (int j = 1; j < 8; ++j) absmax = fmaxf(absmax, red[j]);
    absmax = fmaxf(absmax, 1e-20f);
    const float sx = absmax * (1.0f / 127.0f);
    const float inv_dx = 127.0f / absmax;
    __syncthreads();                    // red (aliased with tvs) fully read

    // ---- phase 2: quantize slice to s8 smem A [row][c] (L2-hot re-read) ----
    {
        char* arow = smem + SM_AS + (size_t)trow * A_ST_B + cg * 128;
#pragma unroll 4
        for (int u = 0; u < 32; ++u) {
            uint32_t acc = 0;
#pragma unroll
            for (int b = 0; b < 4; ++b) {
                const float v = __ldg(xrow + (size_t)(cg * 128 + u * 4 + b) * TD);
                int q = __float2int_rn(v * inv_dx);
                q = max(-127, min(127, q));
                acc |= (uint32_t)(q & 255) << (8 * b);
            }
            *reinterpret_cast<uint32_t*>(arow + u * 4) = acc;
        }
    }
#pragma unroll
    for (int s = 0; s < 16; ++s) tvs[s * 256 + tid] = -INFINITY;
#pragma unroll
    for (int s = 0; s < 16; ++s) tis[s * 256 + tid] = 0;

    // B staging: chunk = 128 codes x 128 k-bytes = 1024 x 16B; 4/thread
    uint4 pb[4];
    auto b_fetch = [&](int ntile, int kb) {
#pragma unroll
        for (int i = 0; i < 4; ++i) {
            const int idx = tid + i * 256;
            pb[i] = *reinterpret_cast<const uint4*>(
                g_cb_s8 + (size_t)(ntile * 128 + (idx >> 3)) * CD + kb * 128 +
                (idx & 7) * 16);
        }
    };
    auto b_store = [&]() {
        char* B = smem + SM_BS;
#pragma unroll
        for (int i = 0; i < 4; ++i) {
            const int idx = tid + i * 256;
            *reinterpret_cast<uint4*>(B + (size_t)(idx >> 3) * B_ST_B + (idx & 7) * 16) = pb[i];
        }
    };

    b_fetch(0, 0);
    b_store();
    __syncthreads();     // A staged + lists init + B chunk 0 ready

    int acc[2][4][4];
    // ---- main: 32 chunks (8 ntiles x 4 k-quarters), single B buffer ----
    for (int gk = 0; gk < 32; ++gk) {
        const int kb = gk & 3;
        if (kb == 0) {
#pragma unroll
            for (int a = 0; a < 2; ++a)
#pragma unroll
                for (int b = 0; b < 4; ++b)
#pragma unroll
                    for (int c = 0; c < 4; ++c) acc[a][b][c] = 0;
        }
        if (gk < 31) b_fetch((gk + 1) >> 2, (gk + 1) & 3);   // gmem -> regs (overlaps MMA)

#pragma unroll
        for (int s = 0; s < 4; ++s) {                 // k32 steps in 128B chunk
            uint32_t bf[2][4];
            ldsm_x4(bf[0], b_base + (uint32_t)((wn * 32 +  0) * B_ST_B + s * 32) + b_lane_off);
            ldsm_x4(bf[1], b_base + (uint32_t)((wn * 32 + 16) * B_ST_B + s * 32) + b_lane_off);
#pragma unroll
            for (int mt = 0; mt < 2; ++mt) {
                uint32_t af[4];
                ldsm_x4(af, a_base +
                    (uint32_t)((wm * 32 + mt * 16) * A_ST_B + kb * 128 + s * 32) +
                    a_lane_off);
                imma16832(acc[mt][0], af, &bf[0][0]);
                imma16832(acc[mt][1], af, &bf[0][2]);
                imma16832(acc[mt][2], af, &bf[1][0]);
                imma16832(acc[mt][3], af, &bf[1][2]);
            }
        }

        if (kb == 3) {   // fold finished ntile into per-lane top-4 lists
            const int Nb = (gk >> 2) * 128;
#pragma unroll
            for (int nt = 0; nt < 4; ++nt) {
                const int c2 = Nb + wn * 32 + nt * 8 + 2 * t4;
                const float s0 = sx * __ldg(&g_cscale[c2]);
                const float s1 = sx * __ldg(&g_cscale[c2 + 1]);
                const float h0 = __ldg(&g_half_hat[c2]);
                const float h1 = __ldg(&g_half_hat[c2 + 1]);
#pragma unroll
                for (int mt = 0; mt < 2; ++mt) {
                    ins4(tvs, tis, tid, mt * 2,     (float)acc[mt][nt][0] * s0 - h0, c2);
                    ins4(tvs, tis, tid, mt * 2,     (float)acc[mt][nt][1] * s1 - h1, c2 + 1);
                    ins4(tvs, tis, tid, mt * 2 + 1, (float)acc[mt][nt][2] * s0 - h0, c2);
                    ins4(tvs, tis, tid, mt * 2 + 1, (float)acc[mt][nt][3] * s1 - h1, c2 + 1);
                }
            }
        }
        __syncthreads();                              // all readers done with B
        if (gk < 31) {
            b_store();                                // regs -> B buffer
            __syncthreads();                          // B ready for next chunk
        }
    }

    float* mv = reinterpret_cast<float*>(smem + SM_MV);   // [row][wn][8]
    int*   mi = reinterpret_cast<int*>(smem + SM_MI);

    // quad merge (lanes t4=0..3 share rows) -> top-8, one lane writes per slot
#pragma unroll
    for (int slot = 0; slot < 4; ++slot) {
        float v8[8]; int i8[8];
#pragma unroll
        for (int j = 0; j < 4; ++j) {
            v8[j] = tvs[(slot * 4 + j) * 256 + tid];
            i8[j] = (int)tis[(slot * 4 + j) * 256 + tid];
        }
#pragma unroll
        for (int j = 4; j < 8; ++j) { v8[j] = -INFINITY; i8[j] = 0; }
#pragma unroll
        for (int off = 1; off <= 2; off <<= 1) {
            float ov[8]; int oi[8];
#pragma unroll
            for (int j = 0; j < 8; ++j) {
                ov[j] = __shfl_xor_sync(~0u, v8[j], off);
                oi[j] = __shfl_xor_sync(~0u, i8[j], off);
            }
#pragma unroll
            for (int j = 0; j < 8; ++j) rins8(v8, i8, ov[j], oi[j]);
        }
        if (t4 == 0) {
            const int row = wm * 32 + (slot >> 1) * 16 + g8 + (slot & 1) * 8;
            const int e = (row * 4 + wn) * 8;
#pragma unroll
            for (int j = 0; j < 8; ++j) { mv[e + j] = v8[j]; mi[e + j] = i8[j]; }
        }
    }
    __syncthreads();

    float* fv  = reinterpret_cast<float*>(smem + SM_FV);   // [row][8]
    int*   fi  = reinterpret_cast<int*>(smem + SM_FI);
    int*   bix = reinterpret_cast<int*>(smem + SM_BIX);

    if (tid < 64) {      // final per-row merge of the 4 wn-lists -> top-8
        float v8[8]; int i8[8];
#pragma unroll
        for (int j = 0; j < 8; ++j) { v8[j] = -INFINITY; i8[j] = 0; }
#pragma unroll
        for (int e = 0; e < 32; ++e)
            rins8(v8, i8, mv[tid * 32 + e], mi[tid * 32 + e]);
#pragma unroll
        for (int j = 0; j < 8; ++j) { fv[tid * 8 + j] = v8[j]; fi[tid * 8 + j] = i8[j]; }
    }
    __syncthreads();

    // ---- exact fp32 rescore: QUAD = 4 adjacent lanes of one warp per row.
    // Gate (svm >= thr) is row-uniform -> quad-convergent shuffles are safe.
    {
        const int rrow = wid * 8 + (lane >> 2);   // 8 warps x 8 rows = 64
        const int qcg  = lane & 3;
        const unsigned qmask = 0xFu << (lane & ~3);
        const float* xr = x + (size_t)n * CD * TD + t0 + rrow;

        const float thr = fv[rrow * 8] - MARGIN;
        float best = -INFINITY;
        int   bidx = fi[rrow * 8];
#pragma unroll
        for (int m = 0; m < TOPK; ++m) {
            const float svm = fv[rrow * 8 + m];
            if (m == 0 || svm >= thr) {
                const int k = fi[rrow * 8 + m];
                const float* cr = cb + (size_t)k * CD + qcg * 128;
                float a = 0.0f;
#pragma unroll 8
                for (int i = 0; i < 128; ++i)
                    a = fmaf(__ldg(xr + (size_t)(qcg * 128 + i) * TD), __ldg(cr + i), a);
                a += __shfl_xor_sync(qmask, a, 1);
                a += __shfl_xor_sync(qmask, a, 2);
                const float s = a - __ldg(&g_half_exact[k]);
                if (s > best || (s == best && k < bidx)) { best = s; bidx = k; }
            }
        }
        if (qcg == 0) bix[rrow] = bidx;
    }
    __syncthreads();

    // ---- gather-write: thread (cg, trow); stores coalesced over t ----
    {
        const int bidx = bix[trow];
        const float4* cr4 = reinterpret_cast<const float4*>(cb + (size_t)bidx * CD + cg * 128);
        float* ob = out + (size_t)n * CD * TD + t0 + trow;
#pragma unroll 4
        for (int i = 0; i < 32; ++i) {
            const float4 w = __ldg(cr4 + i);
            const int c = cg * 128 + i * 4;
            ob[(size_t)(c + 0) * TD] = w.x;
            ob[(size_t)(c + 1) * TD] = w.y;
            ob[(size_t)(c + 2) * TD] = w.z;
            ob[(size_t)(c + 3) * TD] = w.w;
        }
    }
    if (blockIdx.x == 0 && tid == 0) {   // scalar tail (commit_loss, perplexity)
        for (long long e = XD_ELEMS; e < out_size; ++e) out[e] = 0.0f;
    }
}

// ===========================================================================
extern "C" void kernel_launch(void* const* d_in, const int* in_sizes, int n_in,
                              void* d_out, int out_size)
{
    const float* x  = (const float*)d_in[0];
    const float* cb = (const float*)d_in[1];
    if (n_in >= 2 && in_sizes[0] < in_sizes[1]) {
        const float* tmp = x; x = cb; cb = tmp;
    }
    float* out = (float*)d_out;

    cudaFuncSetAttribute(vq_fused_kernel,
                         cudaFuncAttributeMaxDynamicSharedMemorySize, SM_TOTAL);

    vq_prep_kernel<<<KC, 128>>>(cb);
    vq_fused_kernel<<<N_CTAS, 256, SM_TOTAL>>>(x, cb, out, (long long)out_size);
}

// round 11
// speedup vs baseline: 2.2244x; 1.1029x over previous
#include <cuda_runtime.h>
#include <stdint.h>
#include <math.h>

// Shapes (fixed): x [32, 512, 2048] f32, codebook [1024, 512] f32.
#define NB 32
#define CD 512
#define TD 2048
#define KC 1024
#define NT_ROWS (NB * TD)
#define XD_ELEMS ((long long)NB * CD * TD)

#define ROWS_PER_CTA 64
#define N_CTAS (NT_ROWS / ROWS_PER_CTA)    // 1024
#define TOPK 8
#define MARGIN 3.5f

// smem layout (bytes) — A + lists only; B comes from L2 as prebuilt fragments
#define A_ST_B 528                  // 512 s8 + 16 pad (528%128=16 -> LDSM conflict-free)
#define SM_AS 0                     // A: 64*528 = 33792
#define SM_TV 33792                 // per-lane top-4 vals, 4 slots: 16*256*4 = 16384
#define SM_TI (SM_TV + 16384)       // 50176: idx u16: 16*256*2 = 8192
#define SM_TOTAL (SM_TI + 8192)     // 58368 -> 3 CTAs/SM comfortably
// aliased regions (non-overlapping lifetimes):
#define SM_RED SM_TV                // absmax reduce (8 floats); dead before list init
#define SM_MV SM_AS                 // merge scratch in A region (A dead after main loop)
#define SM_MI (SM_AS + 8192)
#define SM_FV SM_TV                 // final per-row top8 (tvs dead after quad merge)
#define SM_FI (SM_TV + 2048)
#define SM_BIX (SM_TV + 4096)       // winning idx per row

// ---- global scratch (no cudaMalloc allowed) ----
__device__ __align__(16) unsigned char g_cb_s8[KC * CD];     // 512 KB quantized codebook
__device__ __align__(16) uint4 g_cb_frag[64 * 16 * 32];      // 512 KB B fragments
                                                             // [c16 0..63][ks 0..15][lane]
__device__ float g_cscale[KC];        // per-code quant scale (absmax/127)
__device__ float g_half_hat[KC];      // 0.5*||c_hat||^2 (dequantized-code norm)
__device__ float g_half_exact[KC];    // 0.5*||c||^2 fp32 (rescore)

// ===========================================================================
// Prep 1: per-code absmax scale, s8 quantize, exact + hat half-norms.
// ===========================================================================
__global__ void vq_prep_kernel(const float* __restrict__ cb)
{
    const int k = blockIdx.x;
    const int tid = threadIdx.x;                    // 128 threads x float4
    const float4 v = reinterpret_cast<const float4*>(cb + (size_t)k * CD)[tid];

    float am = fmaxf(fmaxf(fabsf(v.x), fabsf(v.y)), fmaxf(fabsf(v.z), fabsf(v.w)));
    float se = v.x * v.x + v.y * v.y + v.z * v.z + v.w * v.w;
#pragma unroll
    for (int o = 16; o > 0; o >>= 1) {
        am = fmaxf(am, __shfl_xor_sync(~0u, am, o));
        se += __shfl_xor_sync(~0u, se, o);
    }
    __shared__ float wam[4], wse[4];
    __shared__ int   wsq[4];
    if ((tid & 31) == 0) { wam[tid >> 5] = am; wse[tid >> 5] = se; }
    __syncthreads();
    const float absmax = fmaxf(fmaxf(fmaxf(wam[0], wam[1]), fmaxf(wam[2], wam[3])), 1e-20f);
    const float inv = 127.0f / absmax;

    int q0 = max(-127, min(127, __float2int_rn(v.x * inv)));
    int q1 = max(-127, min(127, __float2int_rn(v.y * inv)));
    int q2 = max(-127, min(127, __float2int_rn(v.z * inv)));
    int q3 = max(-127, min(127, __float2int_rn(v.w * inv)));
    uint32_t w = (uint32_t)(q0 & 255) | ((uint32_t)(q1 & 255) << 8) |
                 ((uint32_t)(q2 & 255) << 16) | ((uint32_t)(q3 & 255) << 24);
    reinterpret_cast<uint32_t*>(g_cb_s8)[(size_t)k * (CD / 4) + tid] = w;

    int sq = q0 * q0 + q1 * q1 + q2 * q2 + q3 * q3;
#pragma unroll
    for (int o = 16; o > 0; o >>= 1) sq += __shfl_xor_sync(~0u, sq, o);
    if ((tid & 31) == 0) wsq[tid >> 5] = sq;
    __syncthreads();
    if (tid == 0) {
        const float sc = absmax / 127.0f;
        g_cscale[k]     = sc;
        g_half_exact[k] = 0.5f * (wse[0] + wse[1] + wse[2] + wse[3]);
        g_half_hat[k]   = 0.5f * sc * sc * (float)(wsq[0] + wsq[1] + wsq[2] + wsq[3]);
    }
}

// ---------------------------------------------------------------------------
__device__ __forceinline__ void ldsm_x4(uint32_t* r, uint32_t addr)
{
    asm volatile("ldmatrix.sync.aligned.m8n8.x4.shared.b16 {%0,%1,%2,%3}, [%4];"
                 : "=r"(r[0]), "=r"(r[1]), "=r"(r[2]), "=r"(r[3]) : "r"(addr));
}
__device__ __forceinline__ uint32_t smem_u32(const void* p)
{
    uint32_t a;
    asm("{ .reg .u64 t; cvta.to.shared.u64 t, %1; cvt.u32.u64 %0, t; }"
        : "=r"(a) : "l"(p));
    return a;
}

// ===========================================================================
// Prep 2: build B fragments with the SAME smem layout + ldmatrix lane pattern
// the fused kernel used when it staged B itself -> bit-identical fragments.
// 64 blocks x 128 thr; block b handles codes [b*16, b*16+16) x all 16 ksteps.
// ===========================================================================
__global__ void vq_frag_kernel()
{
    __shared__ __align__(16) char bs[16 * A_ST_B];   // 16 code rows, stride 528
    const int tid  = threadIdx.x;
    const int lane = tid & 31;
    const int wrp  = tid >> 5;                       // 0..3
    const int c0   = blockIdx.x * 16;

    // stage 16 rows x 512B (linear within row)
    for (int idx = tid; idx < 16 * 32; idx += 128) { // 16B units
        const int row = idx >> 5, u = idx & 31;
        *reinterpret_cast<uint4*>(bs + row * A_ST_B + u * 16) =
            *reinterpret_cast<const uint4*>(g_cb_s8 + (size_t)(c0 + row) * CD + u * 16);
    }
    __syncthreads();

    const uint32_t base = smem_u32(bs);
    const uint32_t lane_off =
        (uint32_t)((lane & 7) * A_ST_B + ((lane >> 3) & 1) * 16 +
                   (lane >> 4) * (8 * A_ST_B));
    for (int j = 0; j < 4; ++j) {
        const int ks = wrp * 4 + j;                  // k-step (32 bytes)
        uint32_t bf[4];
        ldsm_x4(bf, base + (uint32_t)(ks * 32) + lane_off);
        g_cb_frag[((size_t)blockIdx.x * 16 + ks) * 32 + lane] =
            make_uint4(bf[0], bf[1], bf[2], bf[3]);
    }
}

// ---------------------------------------------------------------------------
__device__ __forceinline__ void imma16832(int* d, const uint32_t* a,
                                          uint32_t b0, uint32_t b1)
{
    asm volatile(
        "mma.sync.aligned.m16n8k32.row.col.s32.s8.s8.s32 "
        "{%0,%1,%2,%3}, {%4,%5,%6,%7}, {%8,%9}, {%0,%1,%2,%3};"
        : "+r"(d[0]), "+r"(d[1]), "+r"(d[2]), "+r"(d[3])
        : "r"(a[0]), "r"(a[1]), "r"(a[2]), "r"(a[3]), "r"(b0), "r"(b1));
}

// sorted-desc insert into 4-entry smem list (vals f32 [slot*4+j][256], idx u16)
__device__ __forceinline__ void ins4(float* tvs, unsigned short* tis, int tid,
                                     int slot, float v, int idx)
{
    const int b = (slot << 2) * 256 + tid;
    if (v > tvs[b + 768]) {
        const float v0 = tvs[b], v1 = tvs[b + 256], v2 = tvs[b + 512];
        const unsigned short i0 = tis[b], i1 = tis[b + 256], i2 = tis[b + 512];
        if (v > v2) {
            tvs[b + 768] = v2; tis[b + 768] = i2;
            if (v > v1) {
                tvs[b + 512] = v1; tis[b + 512] = i1;
                if (v > v0) {
                    tvs[b + 256] = v0; tis[b + 256] = i0;
                    tvs[b] = v; tis[b] = (unsigned short)idx;
                } else { tvs[b + 256] = v; tis[b + 256] = (unsigned short)idx; }
            } else { tvs[b + 512] = v; tis[b + 512] = (unsigned short)idx; }
        } else { tvs[b + 768] = v; tis[b + 768] = (unsigned short)idx; }
    }
}
// reg-side sorted-desc insert into 8-entry list
__device__ __forceinline__ void rins8(float* v, int* i, float nv, int ni)
{
    if (nv > v[7]) {
        v[7] = nv; i[7] = ni;
#pragma unroll
        for (int p = 7; p > 0; --p) {
            if (v[p] > v[p - 1]) {
                const float tv = v[p - 1]; v[p - 1] = v[p]; v[p] = tv;
                const int   ti = i[p - 1]; i[p - 1] = i[p]; i[p] = ti;
            }
        }
    }
}

// ===========================================================================
// Fused: per-CTA x-scale -> s8 quantize -> IMMA screen (B fragments straight
// from L2, ZERO main-loop barriers) -> top-8 -> exact fp32 rescore -> gather.
// 1024 CTAs x 256 thr; 3 CTAs/SM. Warp grid 2(wm) x 4(wn), tile 32x32.
// ===========================================================================
__global__ __launch_bounds__(256, 3) void vq_fused_kernel(
    const float* __restrict__ x, const float* __restrict__ cb,
    float* __restrict__ out, long long out_size)
{
    extern __shared__ __align__(16) char smem[];
    float*          tvs = reinterpret_cast<float*>(smem + SM_TV);
    unsigned short* tis = reinterpret_cast<unsigned short*>(smem + SM_TI);
    float*          red = reinterpret_cast<float*>(smem + SM_RED);

    const uint32_t a_base = smem_u32(smem) + SM_AS;

    const int tid  = threadIdx.x;
    const int lane = tid & 31;
    const int wid  = tid >> 5;
    const int wm   = wid >> 2;          // 0..1 (32 rows each)
    const int wn   = wid & 3;           // 0..3 (32 codes each)
    const int g8   = lane >> 2;         // 0..7
    const int t4   = lane & 3;          // 0..3

    const uint32_t a_lane_off =
        (uint32_t)(((lane & 7) + ((lane >> 3) & 1) * 8) * A_ST_B + (lane >> 4) * 16);

    const int r0 = blockIdx.x * ROWS_PER_CTA;
    const int n  = r0 >> 11;
    const int t0 = r0 & (TD - 1);

    const int trow = tid & 63;          // staging/gather row within slice
    const int cg   = tid >> 6;          // 0..3: 128-channel group
    const float* xrow = x + (size_t)n * CD * TD + t0 + trow;

    // ---- phase 1: per-CTA absmax over the 64x512 slice ----
    float am = 0.0f;
#pragma unroll 8
    for (int i = 0; i < 128; ++i)
        am = fmaxf(am, fabsf(__ldg(xrow + (size_t)(cg * 128 + i) * TD)));
#pragma unroll
    for (int o = 16; o > 0; o >>= 1) am = fmaxf(am, __shfl_xor_sync(~0u, am, o));
    if (lane == 0) red[wid] = am;
    __syncthreads();
    float absmax = red[0];
#pragma unroll
    for (int j = 1; j < 8; ++j) absmax = fmaxf(absmax, red[j]);
    absmax = fmaxf(absmax, 1e-20f);
    const float sx = absmax * (1.0f / 127.0f);
    const float inv_dx = 127.0f / absmax;
    __syncthreads();                    // red (aliased with tvs) fully read

    // ---- phase 2: quantize slice to s8 smem A [row][c] (L2-hot re-read) ----
    {
        char* arow = smem + SM_AS + (size_t)trow * A_ST_B + cg * 128;
#pragma unroll 4
        for (int u = 0; u < 32; ++u) {
            uint32_t acc = 0;
#pragma unroll
            for (int b = 0; b < 4; ++b) {
                const float v = __ldg(xrow + (size_t)(cg * 128 + u * 4 + b) * TD);
                int q = __float2int_rn(v * inv_dx);
                q = max(-127, min(127, q));
                acc |= (uint32_t)(q & 255) << (8 * b);
            }
            *reinterpret_cast<uint32_t*>(arow + u * 4) = acc;
        }
    }
#pragma unroll
    for (int s = 0; s < 16; ++s) tvs[s * 256 + tid] = -INFINITY;
#pragma unroll
    for (int s = 0; s < 16; ++s) tis[s * 256 + tid] = 0;
    __syncthreads();                    // A staged + lists init

    // ---- main loop: NO barriers. B fragments from L2, A via ldmatrix ----
    int acc[2][4][4];
    for (int nb = 0; nb < 8; ++nb) {
#pragma unroll
        for (int a = 0; a < 2; ++a)
#pragma unroll
            for (int b = 0; b < 4; ++b)
#pragma unroll
                for (int c = 0; c < 4; ++c) acc[a][b][c] = 0;

        // fragment pointers for this warp's 32 codes (two c16 groups)
        const uint4* f0 = g_cb_frag + ((size_t)(nb * 8 + wn * 2 + 0) * 16) * 32 + lane;
        const uint4* f1 = g_cb_frag + ((size_t)(nb * 8 + wn * 2 + 1) * 16) * 32 + lane;

#pragma unroll 4
        for (int ks = 0; ks < 16; ++ks) {
            const uint4 B0 = __ldg(f0 + ks * 32);
            const uint4 B1 = __ldg(f1 + ks * 32);
            uint32_t af0[4], af1[4];
            ldsm_x4(af0, a_base + (uint32_t)((wm * 32 +  0) * A_ST_B + ks * 32) + a_lane_off);
            ldsm_x4(af1, a_base + (uint32_t)((wm * 32 + 16) * A_ST_B + ks * 32) + a_lane_off);
            imma16832(acc[0][0], af0, B0.x, B0.y);
            imma16832(acc[0][1], af0, B0.z, B0.w);
            imma16832(acc[0][2], af0, B1.x, B1.y);
            imma16832(acc[0][3], af0, B1.z, B1.w);
            imma16832(acc[1][0], af1, B0.x, B0.y);
            imma16832(acc[1][1], af1, B0.z, B0.w);
            imma16832(acc[1][2], af1, B1.x, B1.y);
            imma16832(acc[1][3], af1, B1.z, B1.w);
        }

        // fold this ntile into per-lane top-4 lists (tid-private -> no sync)
        const int Nb = nb * 128;
#pragma unroll
        for (int nt = 0; nt < 4; ++nt) {
            const int c2 = Nb + wn * 32 + nt * 8 + 2 * t4;
            const float s0 = sx * __ldg(&g_cscale[c2]);
            const float s1 = sx * __ldg(&g_cscale[c2 + 1]);
            const float h0 = __ldg(&g_half_hat[c2]);
            const float h1 = __ldg(&g_half_hat[c2 + 1]);
#pragma unroll
            for (int mt = 0; mt < 2; ++mt) {
                ins4(tvs, tis, tid, mt * 2,     (float)acc[mt][nt][0] * s0 - h0, c2);
                ins4(tvs, tis, tid, mt * 2,     (float)acc[mt][nt][1] * s1 - h1, c2 + 1);
                ins4(tvs, tis, tid, mt * 2 + 1, (float)acc[mt][nt][2] * s0 - h0, c2);
                ins4(tvs, tis, tid, mt * 2 + 1, (float)acc[mt][nt][3] * s1 - h1, c2 + 1);
            }
        }
    }
    __syncthreads();     // all folds done; A region now reusable as merge scratch

    float* mv = reinterpret_cast<float*>(smem + SM_MV);   // [row][wn][8]
    int*   mi = reinterpret_cast<int*>(smem + SM_MI);

    // quad merge (lanes t4=0..3 share rows) -> top-8, one lane writes per slot
#pragma unroll
    for (int slot = 0; slot < 4; ++slot) {
        float v8[8]; int i8[8];
#pragma unroll
        for (int j = 0; j < 4; ++j) {
            v8[j] = tvs[(slot * 4 + j) * 256 + tid];
            i8[j] = (int)tis[(slot * 4 + j) * 256 + tid];
        }
#pragma unroll
        for (int j = 4; j < 8; ++j) { v8[j] = -INFINITY; i8[j] = 0; }
#pragma unroll
        for (int off = 1; off <= 2; off <<= 1) {
            float ov[8]; int oi[8];
#pragma unroll
            for (int j = 0; j < 8; ++j) {
                ov[j] = __shfl_xor_sync(~0u, v8[j], off);
                oi[j] = __shfl_xor_sync(~0u, i8[j], off);
            }
#pragma unroll
            for (int j = 0; j < 8; ++j) rins8(v8, i8, ov[j], oi[j]);
        }
        if (t4 == 0) {
            const int row = wm * 32 + (slot >> 1) * 16 + g8 + (slot & 1) * 8;
            const int e = (row * 4 + wn) * 8;
#pragma unroll
            for (int j = 0; j < 8; ++j) { mv[e + j] = v8[j]; mi[e + j] = i8[j]; }
        }
    }
    __syncthreads();

    float* fv  = reinterpret_cast<float*>(smem + SM_FV);   // [row][8]
    int*   fi  = reinterpret_cast<int*>(smem + SM_FI);
    int*   bix = reinterpret_cast<int*>(smem + SM_BIX);

    if (tid < 64) {      // final per-row merge of the 4 wn-lists -> top-8
        float v8[8]; int i8[8];
#pragma unroll
        for (int j = 0; j < 8; ++j) { v8[j] = -INFINITY; i8[j] = 0; }
#pragma unroll
        for (int e = 0; e < 32; ++e)
            rins8(v8, i8, mv[tid * 32 + e], mi[tid * 32 + e]);
#pragma unroll
        for (int j = 0; j < 8; ++j) { fv[tid * 8 + j] = v8[j]; fi[tid * 8 + j] = i8[j]; }
    }
    __syncthreads();

    // ---- exact fp32 rescore: QUAD = 4 adjacent lanes of one warp per row.
    // Gate (svm >= thr) is row-uniform -> quad-convergent shuffles are safe.
    {
        const int rrow = wid * 8 + (lane >> 2);   // 8 warps x 8 rows = 64
        const int qcg  = lane & 3;
        const unsigned qmask = 0xFu << (lane & ~3);
        const float* xr = x + (size_t)n * CD * TD + t0 + rrow;

        const float thr = fv[rrow * 8] - MARGIN;
        float best = -INFINITY;
        int   bidx = fi[rrow * 8];
#pragma unroll
        for (int m = 0; m < TOPK; ++m) {
            const float svm = fv[rrow * 8 + m];
            if (m == 0 || svm >= thr) {
                const int k = fi[rrow * 8 + m];
                const float* cr = cb + (size_t)k * CD + qcg * 128;
                float a = 0.0f;
#pragma unroll 8
                for (int i = 0; i < 128; ++i)
                    a = fmaf(__ldg(xr + (size_t)(qcg * 128 + i) * TD), __ldg(cr + i), a);
                a += __shfl_xor_sync(qmask, a, 1);
                a += __shfl_xor_sync(qmask, a, 2);
                const float s = a - __ldg(&g_half_exact[k]);
                if (s > best || (s == best && k < bidx)) { best = s; bidx = k; }
            }
        }
        if (qcg == 0) bix[rrow] = bidx;
    }
    __syncthreads();

    // ---- gather-write: thread (cg, trow); stores coalesced over t ----
    {
        const int bidx = bix[trow];
        const float4* cr4 = reinterpret_cast<const float4*>(cb + (size_t)bidx * CD + cg * 128);
        float* ob = out + (size_t)n * CD * TD + t0 + trow;
#pragma unroll 4
        for (int i = 0; i < 32; ++i) {
            const float4 w = __ldg(cr4 + i);
            const int c = cg * 128 + i * 4;
            ob[(size_t)(c + 0) * TD] = w.x;
            ob[(size_t)(c + 1) * TD] = w.y;
            ob[(size_t)(c + 2) * TD] = w.z;
            ob[(size_t)(c + 3) * TD] = w.w;
        }
    }
    if (blockIdx.x == 0 && tid == 0) {   // scalar tail (commit_loss, perplexity)
        for (long long e = XD_ELEMS; e < out_size; ++e) out[e] = 0.0f;
    }
}

// ===========================================================================
extern "C" void kernel_launch(void* const* d_in, const int* in_sizes, int n_in,
                              void* d_out, int out_size)
{
    const float* x  = (const float*)d_in[0];
    const float* cb = (const float*)d_in[1];
    if (n_in >= 2 && in_sizes[0] < in_sizes[1]) {
        const float* tmp = x; x = cb; cb = tmp;
    }
    float* out = (float*)d_out;

    cudaFuncSetAttribute(vq_fused_kernel,
                         cudaFuncAttributeMaxDynamicSharedMemorySize, SM_TOTAL);

    vq_prep_kernel<<<KC, 128>>>(cb);
    vq_frag_kernel<<<64, 128>>>();
    vq_fused_kernel<<<N_CTAS, 256, SM_TOTAL>>>(x, cb, out, (long long)out_size);
}